// round 2
// baseline (speedup 1.0000x reference)
#include <cuda_runtime.h>
#include <cstdint>
#include <cstddef>

// Problem constants
#define T_STEPS 1024
#define BATCH   64
#define DDIM    128
#define HDIM    512
#define KAUG    (HDIM + DDIM)   // 640: augmented K = [fr | x]
#define ALPHA   0.1f

// Decomposition: 16 clusters x 8 CTAs. Cluster owns 4 batches; CTA owns 64 outputs.
#define CLUSTER 8
#define GPC     64               // outputs (g) per CTA
#define BPC     4                // batches per cluster
#define NTHR    512
#define WPAD    68               // padded W row (floats)

#define W_FLOATS    (KAUG * WPAD)        // 43520 (170 KB)
#define ABUF_FLOATS (KAUG * BPC)         // 2560 per buffer, ping-pong x2
#define RED_FLOATS  (16 * GPC * BPC)     // 4096
#define SMEM_FLOATS (W_FLOATS + 2*ABUF_FLOATS + RED_FLOATS + GPC)
#define SMEM_BYTES  (SMEM_FLOATS * 4)    // 211,456 B < 227 KB opt-in

// ---- Blackwell packed fp32x2 FMA ----
__device__ __forceinline__ unsigned long long fma2(unsigned long long a,
                                                   unsigned long long b,
                                                   unsigned long long c) {
    unsigned long long d;
    asm("fma.rn.f32x2 %0, %1, %2, %3;" : "=l"(d) : "l"(a), "l"(b), "l"(c));
    return d;
}
__device__ __forceinline__ unsigned long long splat2(float x) {
    unsigned long long d;
    asm("mov.b64 %0, {%1, %1};" : "=l"(d) : "f"(x));
    return d;
}
__device__ __forceinline__ float lo32(unsigned long long v) {
    return __uint_as_float((unsigned)(v & 0xFFFFFFFFull));
}
__device__ __forceinline__ float hi32(unsigned long long v) {
    return __uint_as_float((unsigned)(v >> 32));
}

// ---- cluster / DSMEM helpers ----
__device__ __forceinline__ void st_cluster_f32(unsigned addr, float v) {
    asm volatile("st.shared::cluster.f32 [%0], %1;" :: "r"(addr), "f"(v));
}
__device__ __forceinline__ unsigned mapa_u32(unsigned addr, unsigned rank) {
    unsigned d;
    asm("mapa.shared::cluster.u32 %0, %1, %2;" : "=r"(d) : "r"(addr), "r"(rank));
    return d;
}
__device__ __forceinline__ void cluster_sync_() {
    asm volatile("barrier.cluster.arrive.aligned;" ::: "memory");
    asm volatile("barrier.cluster.wait.aligned;" ::: "memory");
}

// Persistent recurrence kernel. One CTA = (cluster cl, rank r):
//   batches  b_global in [cl*4, cl*4+4), outputs g_global in [r*64, r*64+64)
// SMEM: W slice [k(640, pad 68)][g(64)]  (k<512: W_hid[g][k], else W_in[g][k-512])
//       sA ping-pong [2][k(640)][b(4)]   (k<512: fr_t,        else x_t)
//       sRed [16][g 64][b 4], sBias[64]
__global__ void __launch_bounds__(NTHR, 1)
rnn_kernel(const float* __restrict__ input, const float* __restrict__ Win,
           const float* __restrict__ bin,   const float* __restrict__ Whid,
           const float* __restrict__ bhid,  float* __restrict__ out)
{
    extern __shared__ float smem[];
    float* sW    = smem;
    float* sA    = smem + W_FLOATS;
    float* sRed  = sA + 2 * ABUF_FLOATS;
    float* sBias = sRed + RED_FLOATS;

    const int tid  = threadIdx.x;
    const int bx   = blockIdx.x;
    const int rank = bx & (CLUSTER - 1);
    const int cl   = bx >> 3;
    const int b0   = cl * BPC;
    const int g0   = rank * GPC;

    // ---- init: stage augmented weight slice (k-major, transposed) ----
    for (int idx = tid; idx < GPC * KAUG; idx += NTHR) {
        int g = idx / KAUG;
        int k = idx - g * KAUG;
        int gg = g0 + g;
        float w = (k < HDIM) ? Whid[gg * HDIM + k] : Win[gg * DDIM + (k - HDIM)];
        sW[k * WPAD + g] = w;
    }
    if (tid < GPC) sBias[tid] = bhid[g0 + tid] + bin[g0 + tid];

    // buffer 0: fr = relu(0) = 0 ; x = input[t=0]
    for (int k = tid; k < HDIM; k += NTHR) {
        float4 z = {0.f, 0.f, 0.f, 0.f};
        *(float4*)&sA[k * 4] = z;
    }
    if (tid < 256) {
        int b = tid >> 6, d2 = (tid & 63) * 2;
        float2 x = *(const float2*)&input[(size_t)(b0 + b) * DDIM + d2];
        sA[(HDIM + d2) * 4 + b]     = x.x;
        sA[(HDIM + d2 + 1) * 4 + b] = x.y;
    }

    // DSMEM peer base addresses of sA
    unsigned aBase = (unsigned)__cvta_generic_to_shared(sA);
    unsigned pb[CLUSTER];
    #pragma unroll
    for (int c = 0; c < CLUSTER; ++c) pb[c] = mapa_u32(aBase, (unsigned)c);

    __syncthreads();
    cluster_sync_();

    // GEMM mapping: gt (16 threads x 4 g each) x kc (32 chunks of 20 k)
    const int gt  = tid & 15;
    const int kc  = tid >> 4;
    const int kcr = tid >> 5;      // reduced chunk id after intra-warp combine
    const int rg  = tid & 63;      // reducer: output g   (tid < 256)
    const int rb  = tid >> 6;      // reducer: batch  b
    float vreg = 0.0f;             // persistent membrane potential for (rb, rg)

    int cur = 0;
    for (int t = 0; t < T_STEPS; ++t) {
        const float* aBuf = sA + cur * ABUF_FLOATS;

        // ---- fused GEMM: acc[g 4][b-pair 2] over 20 k, f32x2 packed ----
        unsigned long long acc[8];
        #pragma unroll
        for (int i = 0; i < 8; ++i) acc[i] = 0ull;

        const int kbeg = kc * 20;
        #pragma unroll
        for (int kk = 0; kk < 20; ++kk) {
            int k = kbeg + kk;
            float4 w4 = *(const float4*)&sW[k * WPAD + gt * 4];
            unsigned long long a01 = *(const unsigned long long*)&aBuf[k * 4];
            unsigned long long a23 = *(const unsigned long long*)&aBuf[k * 4 + 2];
            unsigned long long wp;
            wp = splat2(w4.x); acc[0] = fma2(wp, a01, acc[0]); acc[1] = fma2(wp, a23, acc[1]);
            wp = splat2(w4.y); acc[2] = fma2(wp, a01, acc[2]); acc[3] = fma2(wp, a23, acc[3]);
            wp = splat2(w4.z); acc[4] = fma2(wp, a01, acc[4]); acc[5] = fma2(wp, a23, acc[5]);
            wp = splat2(w4.w); acc[6] = fma2(wp, a01, acc[6]); acc[7] = fma2(wp, a23, acc[7]);
        }

        // combine kc pairs (lane l <-> l+16 share gt), park partials in smem
        #pragma unroll
        for (int i = 0; i < 4; ++i) {
            float x0 = lo32(acc[i * 2]),     x1 = hi32(acc[i * 2]);
            float x2 = lo32(acc[i * 2 + 1]), x3 = hi32(acc[i * 2 + 1]);
            x0 += __shfl_xor_sync(0xFFFFFFFFu, x0, 16);
            x1 += __shfl_xor_sync(0xFFFFFFFFu, x1, 16);
            x2 += __shfl_xor_sync(0xFFFFFFFFu, x2, 16);
            x3 += __shfl_xor_sync(0xFFFFFFFFu, x3, 16);
            if ((tid & 16) == 0) {
                *(float4*)&sRed[(kcr * GPC + gt * 4 + i) * 4] =
                    make_float4(x0, x1, x2, x3);
            }
        }
        __syncthreads();

        if (tid < 256) {
            // ---- reduce 16 partials, leaky update, relu, store, broadcast ----
            float s = 0.f;
            #pragma unroll
            for (int r = 0; r < 16; ++r) s += sRed[(r * GPC + rg) * 4 + rb];
            vreg = (1.0f - ALPHA) * vreg + ALPHA * (s + sBias[rg]);
            float fr = fmaxf(vreg, 0.f);
            out[((size_t)t * BATCH + (b0 + rb)) * HDIM + (g0 + rg)] = fr;
            // push own fr into every cluster peer's NEXT activation buffer
            unsigned boff = (unsigned)(((cur ^ 1) * ABUF_FLOATS
                                        + (rank * GPC + rg) * 4 + rb) * 4);
            #pragma unroll
            for (int c = 0; c < CLUSTER; ++c) st_cluster_f32(pb[c] + boff, fr);
        } else if (t + 1 < T_STEPS) {
            // ---- prefetch x_{t+1} into NEXT buffer's x region (local) ----
            int u = tid - 256;
            int b = u >> 6, d2 = (u & 63) * 2;
            float2 x = *(const float2*)&input[((size_t)(t + 1) * BATCH + b0 + b) * DDIM + d2];
            float* dst = sA + (cur ^ 1) * ABUF_FLOATS;
            dst[(HDIM + d2) * 4 + b]     = x.x;
            dst[(HDIM + d2 + 1) * 4 + b] = x.y;
        }

        cluster_sync_();   // release pushes / acquire peers'; doubles as CTA barrier
        cur ^= 1;
    }
}

extern "C" void kernel_launch(void* const* d_in, const int* in_sizes, int n_in,
                              void* d_out, int out_size)
{
    const float* input = (const float*)d_in[0];
    const float* Win   = (const float*)d_in[1];
    const float* bin   = (const float*)d_in[2];
    const float* Whid  = (const float*)d_in[3];
    const float* bhid  = (const float*)d_in[4];
    float* out = (float*)d_out;

    cudaFuncSetAttribute(rnn_kernel,
                         cudaFuncAttributeMaxDynamicSharedMemorySize, SMEM_BYTES);

    cudaLaunchConfig_t cfg = {};
    cfg.gridDim  = dim3(16 * CLUSTER, 1, 1);   // 128 CTAs = 16 clusters
    cfg.blockDim = dim3(NTHR, 1, 1);
    cfg.dynamicSmemBytes = SMEM_BYTES;
    cfg.stream = 0;

    cudaLaunchAttribute attr[1];
    attr[0].id = cudaLaunchAttributeClusterDimension;
    attr[0].val.clusterDim.x = CLUSTER;
    attr[0].val.clusterDim.y = 1;
    attr[0].val.clusterDim.z = 1;
    cfg.attrs = attr;
    cfg.numAttrs = 1;

    cudaLaunchKernelEx(&cfg, rnn_kernel, input, Win, bin, Whid, bhid, out);
}

// round 3
// speedup vs baseline: 1.7354x; 1.7354x over previous
#include <cuda_runtime.h>
#include <cstdint>
#include <cstddef>

// Problem constants
#define T_STEPS 1024
#define BATCH   64
#define DDIM    128
#define HDIM    512
#define KAUG    (HDIM + DDIM)   // 640
#define ALPHA   0.1f

// 16 clusters x 8 CTAs. Cluster owns 4 batches; CTA owns 64 outputs.
#define CLUSTER 8
#define GPC     64
#define BPC     4
#define NTHR    512
#define WPAD    68

#define W_FLOATS    (KAUG * WPAD)        // 43520 (170 KB)
#define ABUF_FLOATS (KAUG * BPC)         // 2560 per buffer, ping-pong x2
#define RED_FLOATS  (16 * GPC * BPC)     // 4096
#define SMEM_FLOATS (W_FLOATS + 2*ABUF_FLOATS + RED_FLOATS + GPC)
#define SMEM_BYTES  (SMEM_FLOATS * 4)    // 211,456 B

// ---- Blackwell packed fp32x2 FMA ----
__device__ __forceinline__ unsigned long long fma2(unsigned long long a,
                                                   unsigned long long b,
                                                   unsigned long long c) {
    unsigned long long d;
    asm("fma.rn.f32x2 %0, %1, %2, %3;" : "=l"(d) : "l"(a), "l"(b), "l"(c));
    return d;
}
__device__ __forceinline__ unsigned long long splat2(float x) {
    unsigned long long d;
    asm("mov.b64 %0, {%1, %1};" : "=l"(d) : "f"(x));
    return d;
}
__device__ __forceinline__ float lo32(unsigned long long v) {
    return __uint_as_float((unsigned)(v & 0xFFFFFFFFull));
}
__device__ __forceinline__ float hi32(unsigned long long v) {
    return __uint_as_float((unsigned)(v >> 32));
}
__device__ __forceinline__ unsigned long long pack2(float lo, float hi) {
    unsigned long long d;
    asm("mov.b64 %0, {%1, %2};" : "=l"(d) : "f"(lo), "f"(hi));
    return d;
}

// ---- cluster / DSMEM helpers ----
__device__ __forceinline__ void st_cluster_b64(unsigned addr, unsigned long long v) {
    asm volatile("st.shared::cluster.b64 [%0], %1;" :: "r"(addr), "l"(v));
}
__device__ __forceinline__ unsigned mapa_u32(unsigned addr, unsigned rank) {
    unsigned d;
    asm("mapa.shared::cluster.u32 %0, %1, %2;" : "=r"(d) : "r"(addr), "r"(rank));
    return d;
}
__device__ __forceinline__ void cluster_arrive_() {
    asm volatile("barrier.cluster.arrive.aligned;" ::: "memory");
}
__device__ __forceinline__ void cluster_wait_() {
    asm volatile("barrier.cluster.wait.aligned;" ::: "memory");
}

// Per step (split-phase):
//   a. x-GEMM (k 512..639, local)          <- overlaps previous barrier
//   b. cluster WAIT                        <- peers' fr now visible
//   c. fr-GEMM (k 0..511)
//   d. shfl combine + park sRed
//   d2. warps 8-15: prefetch x_{t+1}
//   e. __syncthreads
//   f. tid<256: coalesced reduce, v-update, relu, STG, packed b64 pushes
//   g. cluster ARRIVE (skipped on last step)
__global__ void __launch_bounds__(NTHR, 1)
rnn_kernel(const float* __restrict__ input, const float* __restrict__ Win,
           const float* __restrict__ bin,   const float* __restrict__ Whid,
           const float* __restrict__ bhid,  float* __restrict__ out)
{
    extern __shared__ float smem[];
    float* sW    = smem;
    float* sA    = smem + W_FLOATS;
    float* sRed  = sA + 2 * ABUF_FLOATS;
    float* sBias = sRed + RED_FLOATS;

    const int tid  = threadIdx.x;
    const int bx   = blockIdx.x;
    const int rank = bx & (CLUSTER - 1);
    const int cl   = bx >> 3;
    const int b0   = cl * BPC;
    const int g0   = rank * GPC;

    // ---- stage weights (pre-scaled by ALPHA), k-major ----
    for (int idx = tid; idx < GPC * KAUG; idx += NTHR) {
        int g = idx / KAUG;
        int k = idx - g * KAUG;
        int gg = g0 + g;
        float w = (k < HDIM) ? Whid[gg * HDIM + k] : Win[gg * DDIM + (k - HDIM)];
        sW[k * WPAD + g] = ALPHA * w;
    }
    if (tid < GPC) sBias[tid] = ALPHA * (bhid[g0 + tid] + bin[g0 + tid]);

    // buffer 0: fr = 0 ; x = input[t=0]
    for (int k = tid; k < HDIM; k += NTHR) {
        float4 z = {0.f, 0.f, 0.f, 0.f};
        *(float4*)&sA[k * 4] = z;
    }
    if (tid < 256) {
        int b = tid >> 6, d2 = (tid & 63) * 2;
        float2 x = *(const float2*)&input[(size_t)(b0 + b) * DDIM + d2];
        sA[(HDIM + d2) * 4 + b]     = x.x;
        sA[(HDIM + d2 + 1) * 4 + b] = x.y;
    }

    unsigned aBase = (unsigned)__cvta_generic_to_shared(sA);
    unsigned pb[CLUSTER];
    #pragma unroll
    for (int c = 0; c < CLUSTER; ++c) pb[c] = mapa_u32(aBase, (unsigned)c);

    __syncthreads();
    cluster_arrive_();            // pairs with WAIT at t=0

    // GEMM mapping: gt (16 x 4g) x kc (32 chunks: 16 fr-k + 4 x-k)
    const int gt  = tid & 15;
    const int kc  = tid >> 4;
    const int kcr = tid >> 5;
    // reducer mapping (coalesced): rg = tid>>2, rb = tid&3
    const int rg  = tid >> 2;
    const int rb  = tid & 3;
    float vreg = 0.0f;

    int cur = 0;
    for (int t = 0; t < T_STEPS; ++t) {
        const float* aBuf = sA + cur * ABUF_FLOATS;

        unsigned long long acc[8];
        #pragma unroll
        for (int i = 0; i < 8; ++i) acc[i] = 0ull;

        // ---- (a) x-part GEMM: local, runs under the barrier's latency ----
        #pragma unroll
        for (int kk = 0; kk < 4; ++kk) {
            int k = HDIM + kc * 4 + kk;
            float4 w4 = *(const float4*)&sW[k * WPAD + gt * 4];
            unsigned long long a01 = *(const unsigned long long*)&aBuf[k * 4];
            unsigned long long a23 = *(const unsigned long long*)&aBuf[k * 4 + 2];
            unsigned long long wp;
            wp = splat2(w4.x); acc[0] = fma2(wp, a01, acc[0]); acc[1] = fma2(wp, a23, acc[1]);
            wp = splat2(w4.y); acc[2] = fma2(wp, a01, acc[2]); acc[3] = fma2(wp, a23, acc[3]);
            wp = splat2(w4.z); acc[4] = fma2(wp, a01, acc[4]); acc[5] = fma2(wp, a23, acc[5]);
            wp = splat2(w4.w); acc[6] = fma2(wp, a01, acc[6]); acc[7] = fma2(wp, a23, acc[7]);
        }

        // ---- (b) wait: peers' fr for step t now visible ----
        cluster_wait_();

        // ---- (c) fr-part GEMM ----
        #pragma unroll
        for (int kk = 0; kk < 16; ++kk) {
            int k = kc * 16 + kk;
            float4 w4 = *(const float4*)&sW[k * WPAD + gt * 4];
            unsigned long long a01 = *(const unsigned long long*)&aBuf[k * 4];
            unsigned long long a23 = *(const unsigned long long*)&aBuf[k * 4 + 2];
            unsigned long long wp;
            wp = splat2(w4.x); acc[0] = fma2(wp, a01, acc[0]); acc[1] = fma2(wp, a23, acc[1]);
            wp = splat2(w4.y); acc[2] = fma2(wp, a01, acc[2]); acc[3] = fma2(wp, a23, acc[3]);
            wp = splat2(w4.z); acc[4] = fma2(wp, a01, acc[4]); acc[5] = fma2(wp, a23, acc[5]);
            wp = splat2(w4.w); acc[6] = fma2(wp, a01, acc[6]); acc[7] = fma2(wp, a23, acc[7]);
        }

        // ---- (d) combine lane pairs (xor 16), park partials ----
        #pragma unroll
        for (int i = 0; i < 4; ++i) {
            float x0 = lo32(acc[i * 2]),     x1 = hi32(acc[i * 2]);
            float x2 = lo32(acc[i * 2 + 1]), x3 = hi32(acc[i * 2 + 1]);
            x0 += __shfl_xor_sync(0xFFFFFFFFu, x0, 16);
            x1 += __shfl_xor_sync(0xFFFFFFFFu, x1, 16);
            x2 += __shfl_xor_sync(0xFFFFFFFFu, x2, 16);
            x3 += __shfl_xor_sync(0xFFFFFFFFu, x3, 16);
            if ((tid & 16) == 0) {
                *(float4*)&sRed[(kcr * GPC + gt * 4 + i) * 4] =
                    make_float4(x0, x1, x2, x3);
            }
        }

        // ---- (d2) warps 8-15 prefetch x_{t+1} into next buffer ----
        if (tid >= 256 && t + 1 < T_STEPS) {
            int u = tid - 256;
            int b = u >> 6, d2 = (u & 63) * 2;
            float2 x = *(const float2*)&input[((size_t)(t + 1) * BATCH + b0 + b) * DDIM + d2];
            float* dst = sA + (cur ^ 1) * ABUF_FLOATS;
            dst[(HDIM + d2) * 4 + b]     = x.x;
            dst[(HDIM + d2 + 1) * 4 + b] = x.y;
        }

        __syncthreads();   // (e)

        if (tid < 256) {
            // ---- (f) coalesced reduce: addr = r*256 + tid, conflict-free ----
            float s = 0.f;
            #pragma unroll
            for (int r = 0; r < 16; ++r) s += sRed[r * 256 + tid];
            vreg = (1.0f - ALPHA) * vreg + (s + sBias[rg]);   // ALPHA pre-folded
            float fr = fmaxf(vreg, 0.f);
            out[((size_t)t * BATCH + (b0 + rb)) * HDIM + (g0 + rg)] = fr;

            if (t + 1 < T_STEPS) {
                // pack (rb, rb+1) pair into b64; even-rb lanes push to 8 peers
                float hi = __shfl_down_sync(0xFFFFFFFFu, fr, 1);
                if ((rb & 1) == 0) {
                    unsigned long long p = pack2(fr, hi);
                    unsigned boff = (unsigned)(((cur ^ 1) * ABUF_FLOATS
                                    + (rank * GPC + rg) * 4 + rb) * 4);
                    #pragma unroll
                    for (int c = 0; c < CLUSTER; ++c) st_cluster_b64(pb[c] + boff, p);
                }
            }
        }

        // ---- (g) arrive: releases pushes; non-reducer warps run ahead ----
        if (t + 1 < T_STEPS) cluster_arrive_();
        cur ^= 1;
    }
}

extern "C" void kernel_launch(void* const* d_in, const int* in_sizes, int n_in,
                              void* d_out, int out_size)
{
    const float* input = (const float*)d_in[0];
    const float* Win   = (const float*)d_in[1];
    const float* bin   = (const float*)d_in[2];
    const float* Whid  = (const float*)d_in[3];
    const float* bhid  = (const float*)d_in[4];
    float* out = (float*)d_out;

    cudaFuncSetAttribute(rnn_kernel,
                         cudaFuncAttributeMaxDynamicSharedMemorySize, SMEM_BYTES);

    cudaLaunchConfig_t cfg = {};
    cfg.gridDim  = dim3(16 * CLUSTER, 1, 1);
    cfg.blockDim = dim3(NTHR, 1, 1);
    cfg.dynamicSmemBytes = SMEM_BYTES;
    cfg.stream = 0;

    cudaLaunchAttribute attr[1];
    attr[0].id = cudaLaunchAttributeClusterDimension;
    attr[0].val.clusterDim.x = CLUSTER;
    attr[0].val.clusterDim.y = 1;
    attr[0].val.clusterDim.z = 1;
    cfg.attrs = attr;
    cfg.numAttrs = 1;

    cudaLaunchKernelEx(&cfg, rnn_kernel, input, Win, bin, Whid, bhid, out);
}

// round 4
// speedup vs baseline: 2.0367x; 1.1736x over previous
#include <cuda_runtime.h>
#include <cstdint>
#include <cstddef>

#define T_STEPS 1024
#define BATCH   64
#define DDIM    128
#define HDIM    512
#define ALPHA   0.1f

// 16 clusters x 8 CTAs; cluster owns 4 batches, CTA owns 64 outputs,
// warp owns 4 outputs x 4 batches, lane owns k-slice (stride 32).
#define CLUSTER 8
#define BPC     4
#define NTHR    512

#define ABUF_FLOATS 2560                  // [k(640)][b(4)] ; k<512 fr, k>=512 x
#define SMEM_BYTES  (2 * ABUF_FLOATS * 4) // ping-pong, 20.5 KB

// ---- packed fp32x2 helpers ----
__device__ __forceinline__ unsigned long long fma2(unsigned long long a,
                                                   unsigned long long b,
                                                   unsigned long long c) {
    unsigned long long d;
    asm("fma.rn.f32x2 %0, %1, %2, %3;" : "=l"(d) : "l"(a), "l"(b), "l"(c));
    return d;
}
__device__ __forceinline__ unsigned long long splat2(float x) {
    unsigned long long d;
    asm("mov.b64 %0, {%1, %1};" : "=l"(d) : "f"(x));
    return d;
}
__device__ __forceinline__ unsigned long long pack2(float lo, float hi) {
    unsigned long long d;
    asm("mov.b64 %0, {%1, %2};" : "=l"(d) : "f"(lo), "f"(hi));
    return d;
}
__device__ __forceinline__ float lo32(unsigned long long v) {
    return __uint_as_float((unsigned)(v & 0xFFFFFFFFull));
}
__device__ __forceinline__ float hi32(unsigned long long v) {
    return __uint_as_float((unsigned)(v >> 32));
}

// ---- cluster helpers ----
__device__ __forceinline__ void st_cluster_b64(unsigned addr, unsigned long long v) {
    asm volatile("st.shared::cluster.b64 [%0], %1;" :: "r"(addr), "l"(v));
}
__device__ __forceinline__ unsigned mapa_u32(unsigned addr, unsigned rank) {
    unsigned d;
    asm("mapa.shared::cluster.u32 %0, %1, %2;" : "=r"(d) : "r"(addr), "r"(rank));
    return d;
}
__device__ __forceinline__ void cluster_arrive_() {
    asm volatile("barrier.cluster.arrive.aligned;" ::: "memory");
}
__device__ __forceinline__ void cluster_wait_() {
    asm volatile("barrier.cluster.wait.aligned;" ::: "memory");
}

__global__ void __launch_bounds__(NTHR, 1)
rnn_kernel(const float* __restrict__ input, const float* __restrict__ Win,
           const float* __restrict__ bin,   const float* __restrict__ Whid,
           const float* __restrict__ bhid,  float* __restrict__ out)
{
    extern __shared__ float sA[];   // [2][640][4]

    const int tid  = threadIdx.x;
    const int lane = tid & 31;
    const int w    = tid >> 5;            // warp 0..15
    const int bx   = blockIdx.x;
    const int rank = bx & (CLUSTER - 1);
    const int cl   = bx >> 3;
    const int b0   = cl * BPC;
    const int g0   = rank * 64;
    const int gbase = g0 + w * 4;         // this warp's 4 hidden units

    // lane's assigned output after the butterfly:
    //   value idx v = b4*8 + b3*4 + b2*2 + b1  (bi = bit i of lane)
    const int vidx = ((lane >> 4) & 1) * 8 + ((lane >> 3) & 1) * 4
                   + ((lane >> 2) & 1) * 2 + ((lane >> 1) & 1);
    const int gl = vidx >> 2;              // 0..3
    const int bb = vidx & 3;               // 0..3
    const int hmine = gbase + gl;

    // ---- load W slice into registers (pre-scaled by ALPHA), g-pair packed ----
    // kk<16: k = kk*32+lane (W_hid) ; kk>=16: k' = (kk-16)*32+lane (W_in)
    unsigned long long wA[20], wB[20];
    #pragma unroll
    for (int kk = 0; kk < 16; ++kk) {
        int k = kk * 32 + lane;
        wA[kk] = pack2(ALPHA * Whid[(gbase + 0) * HDIM + k],
                       ALPHA * Whid[(gbase + 1) * HDIM + k]);
        wB[kk] = pack2(ALPHA * Whid[(gbase + 2) * HDIM + k],
                       ALPHA * Whid[(gbase + 3) * HDIM + k]);
    }
    #pragma unroll
    for (int kk = 16; kk < 20; ++kk) {
        int k = (kk - 16) * 32 + lane;
        wA[kk] = pack2(ALPHA * Win[(gbase + 0) * DDIM + k],
                       ALPHA * Win[(gbase + 1) * DDIM + k]);
        wB[kk] = pack2(ALPHA * Win[(gbase + 2) * DDIM + k],
                       ALPHA * Win[(gbase + 3) * DDIM + k]);
    }
    const float breg = ALPHA * (bhid[hmine] + bin[hmine]);
    float vreg = 0.0f;

    // ---- buffer 0 init: fr = 0 ; x = input[t=0] (warp-partitioned slice) ----
    {
        float4 z = {0.f, 0.f, 0.f, 0.f};
        ((float4*)sA)[tid] = z;                       // fr region: 2048 floats
        int d = w * 8 + (lane >> 2);
        int b = lane & 3;
        sA[(HDIM + d) * 4 + b] = input[(size_t)(b0 + b) * DDIM + d];
    }

    const unsigned aBase = (unsigned)__cvta_generic_to_shared(sA);

    __syncthreads();
    cluster_arrive_();          // pairs with wait at t=0

    const int xd = w * 8 + (lane >> 2);   // my x-staging element
    const int xb = lane & 3;

    int cur = 0;
    for (int t = 0; t < T_STEPS; ++t) {
        cluster_wait_();        // peers' fr(t) + my CTA's x(t) now visible

        // prefetch x(t+1) into a register (STS later, before arrive)
        float xv = 0.f;
        if (t + 1 < T_STEPS)
            xv = input[((size_t)(t + 1) * BATCH + b0 + xb) * DDIM + xd];

        const float* aBuf = sA + cur * ABUF_FLOATS;

        // ---- GEMM: acc[2*b+p] (p: g-pair 0/1), lanes own k strided 32 ----
        unsigned long long acc[8];
        #pragma unroll
        for (int i = 0; i < 8; ++i) acc[i] = 0ull;

        #pragma unroll
        for (int kk = 0; kk < 20; ++kk) {
            int k = (kk < 16) ? (kk * 32 + lane) : (HDIM + (kk - 16) * 32 + lane);
            float4 a4 = *(const float4*)&aBuf[k * 4];    // coalesced, conflict-free
            unsigned long long s0 = splat2(a4.x), s1 = splat2(a4.y);
            unsigned long long s2 = splat2(a4.z), s3 = splat2(a4.w);
            acc[0] = fma2(wA[kk], s0, acc[0]);  acc[1] = fma2(wB[kk], s0, acc[1]);
            acc[2] = fma2(wA[kk], s1, acc[2]);  acc[3] = fma2(wB[kk], s1, acc[3]);
            acc[4] = fma2(wA[kk], s2, acc[4]);  acc[5] = fma2(wB[kk], s2, acc[5]);
            acc[6] = fma2(wA[kk], s3, acc[6]);  acc[7] = fma2(wB[kk], s3, acc[7]);
        }

        // ---- unpack to 16 scalars: v[g*4+b] ----
        float v[16];
        #pragma unroll
        for (int b = 0; b < 4; ++b) {
            v[0 * 4 + b] = lo32(acc[2 * b]);
            v[1 * 4 + b] = hi32(acc[2 * b]);
            v[2 * 4 + b] = lo32(acc[2 * b + 1]);
            v[3 * 4 + b] = hi32(acc[2 * b + 1]);
        }

        // ---- warp-local butterfly: 16 values over 32 lanes ----
        #pragma unroll
        for (int s = 16, cnt = 16; s >= 2; s >>= 1, cnt >>= 1) {
            const bool up = (lane & s) != 0;
            const int half = cnt >> 1;
            #pragma unroll
            for (int i = 0; i < 8; ++i) {
                if (i >= half) break;
                float keep = up ? v[i + half] : v[i];
                float send = up ? v[i] : v[i + half];
                float got  = __shfl_xor_sync(0xFFFFFFFFu, send, s);
                v[i] = keep + got;
            }
        }
        v[0] += __shfl_xor_sync(0xFFFFFFFFu, v[0], 1);
        const float ssum = v[0];   // full dot for output (hmine, bb)

        // ---- leaky update + relu (ALPHA pre-folded into W and bias) ----
        vreg = (1.0f - ALPHA) * vreg + (ssum + breg);
        float fr = fmaxf(vreg, 0.f);
        if ((lane & 1) == 0)
            out[((size_t)t * BATCH + b0 + bb) * HDIM + hmine] = fr;

        if (t + 1 < T_STEPS) {
            // ---- push (b, b^1) pair as b64 to all 8 peers ----
            float frhi = __shfl_xor_sync(0xFFFFFFFFu, fr, 2);  // partner: bb^1
            if ((lane & 3) == 0) {          // 8 lanes: bb even, canonical
                unsigned long long p = pack2(fr, frhi);
                unsigned boff = (unsigned)(((cur ^ 1) * ABUF_FLOATS
                                            + hmine * 4 + bb) * 4);
                #pragma unroll
                for (int c = 0; c < CLUSTER; ++c)
                    st_cluster_b64(mapa_u32(aBase, (unsigned)c) + boff, p);
            }
            // ---- stage x(t+1) into next buffer (local, warp-partitioned) ----
            sA[(cur ^ 1) * ABUF_FLOATS + (HDIM + xd) * 4 + xb] = xv;
            cluster_arrive_();
        }
        cur ^= 1;
    }
}

extern "C" void kernel_launch(void* const* d_in, const int* in_sizes, int n_in,
                              void* d_out, int out_size)
{
    const float* input = (const float*)d_in[0];
    const float* Win   = (const float*)d_in[1];
    const float* bin   = (const float*)d_in[2];
    const float* Whid  = (const float*)d_in[3];
    const float* bhid  = (const float*)d_in[4];
    float* out = (float*)d_out;

    cudaFuncSetAttribute(rnn_kernel,
                         cudaFuncAttributeMaxDynamicSharedMemorySize, SMEM_BYTES);

    cudaLaunchConfig_t cfg = {};
    cfg.gridDim  = dim3(16 * CLUSTER, 1, 1);
    cfg.blockDim = dim3(NTHR, 1, 1);
    cfg.dynamicSmemBytes = SMEM_BYTES;
    cfg.stream = 0;

    cudaLaunchAttribute attr[1];
    attr[0].id = cudaLaunchAttributeClusterDimension;
    attr[0].val.clusterDim.x = CLUSTER;
    attr[0].val.clusterDim.y = 1;
    attr[0].val.clusterDim.z = 1;
    cfg.attrs = attr;
    cfg.numAttrs = 1;

    cudaLaunchKernelEx(&cfg, rnn_kernel, input, Win, bin, Whid, bhid, out);
}